// round 13
// baseline (speedup 1.0000x reference)
#include <cuda_runtime.h>
#include <cuda_bf16.h>
#include <cstdint>
#include <math.h>

// Problem dims
#define TT 128
#define NN 64
#define DD 512
#define HH 512
#define G3 1536   // 3*H

__device__ __forceinline__ float fsigmoid(float x) {
    return 1.0f / (1.0f + __expf(-x));
}
__device__ __forceinline__ float ftanh_fast(float x) {
    float ax = fabsf(x);
    float e = __expf(-2.0f * ax);
    float t = (1.0f - e) / (1.0f + e);
    return copysignf(t, x);
}

// ---------------- mma helpers (baseline PTX, no 'a' features) ----------------
__device__ __forceinline__ uint32_t smem_u32(const void* p) {
    uint32_t a;
    asm("{ .reg .u64 t; cvta.to.shared.u64 t, %1; cvt.u32.u64 %0, t; }" : "=r"(a) : "l"(p));
    return a;
}
__device__ __forceinline__ void ldsm_x4(uint32_t& r0, uint32_t& r1, uint32_t& r2,
                                        uint32_t& r3, uint32_t addr) {
    asm volatile("ldmatrix.sync.aligned.m8n8.x4.shared.b16 {%0,%1,%2,%3}, [%4];"
                 : "=r"(r0), "=r"(r1), "=r"(r2), "=r"(r3) : "r"(addr));
}
__device__ __forceinline__ void mma_bf16(float* d, const uint32_t* a,
                                         uint32_t b0, uint32_t b1) {
    asm volatile("mma.sync.aligned.m16n8k16.row.col.f32.bf16.bf16.f32 "
                 "{%0,%1,%2,%3}, {%4,%5,%6,%7}, {%8,%9}, {%0,%1,%2,%3};"
                 : "+f"(d[0]), "+f"(d[1]), "+f"(d[2]), "+f"(d[3])
                 : "r"(a[0]), "r"(a[1]), "r"(a[2]), "r"(a[3]), "r"(b0), "r"(b1));
}
__device__ __forceinline__ void split2(float a, float b, unsigned& hi, unsigned& lo) {
    __nv_bfloat16 ha = __float2bfloat16(a), hb = __float2bfloat16(b);
    hi = ((unsigned)__bfloat16_as_ushort(hb) << 16) | __bfloat16_as_ushort(ha);
    __nv_bfloat16 la = __float2bfloat16(a - __bfloat162float(ha));
    __nv_bfloat16 lb = __float2bfloat16(b - __bfloat162float(hb));
    lo = ((unsigned)__bfloat16_as_ushort(lb) << 16) | __bfloat16_as_ushort(la);
}

// ---------------- global scratch ----------------
__device__ float g_gi[(size_t)TT * NN * G3];            // gi[m][g]
__device__ unsigned short g_hhi[2][NN * HH];            // ping-pong bf16 h (hi)
__device__ unsigned short g_hlo[2][NN * HH];            // ping-pong bf16 h (lo)

struct __align__(128) PadU { unsigned v; unsigned pad[31]; };
__device__ PadU g_cnt[16];   // 4 row-groups x 4 striped arrival counters

// =====================================================================
// Kernel 1: tensor-core bf16-split GEMM via mma.sync.
// CTA tile 128(m) x 128(g), BK=64, 256 threads = 4x2 warps (32m x 64n).
// =====================================================================
#define BK 64
#define A_STR 72
#define AHI_B 0
#define ALO_B 18432
#define BHI_B 36864
#define BLO_B 55296
#define BIAS_B 73728
#define GM_SMEM (73728 + 512)

__global__ void __launch_bounds__(256, 2) gemm_mma_kernel(
    const float* __restrict__ x,
    const float* __restrict__ w_ih,
    const float* __restrict__ b_ih)
{
    if (blockIdx.x == 0 && blockIdx.y == 0 && threadIdx.x < 16)
        g_cnt[threadIdx.x].v = 0;

    extern __shared__ char sm[];
    const uint32_t sb = smem_u32(sm);
    float* bias = reinterpret_cast<float*>(sm + BIAS_B);

    const int tid = threadIdx.x;
    const int wid = tid >> 5;
    const int l = tid & 31;
    const int g0 = blockIdx.x * 128;
    const int m0 = blockIdx.y * 128;
    const int m_base = (wid & 3) * 32;
    const int n_base = (wid >> 2) * 64;

    if (tid < 128) bias[tid] = b_ih[g0 + tid];

    uint32_t aoff[2], boff[4];
#pragma unroll
    for (int mt = 0; mt < 2; mt++)
        aoff[mt] = ((m_base + mt * 16 + (l & 15)) * A_STR + (l >> 4) * 8) * 2;
#pragma unroll
    for (int p = 0; p < 4; p++)
        boff[p] = ((n_base + p * 16 + (l & 7) + ((l >> 4) & 1) * 8) * A_STR
                   + ((l >> 3) & 1) * 8) * 2;

    float d[2][8][4];
#pragma unroll
    for (int mt = 0; mt < 2; mt++)
#pragma unroll
        for (int nt = 0; nt < 8; nt++)
#pragma unroll
            for (int r = 0; r < 4; r++) d[mt][nt][r] = 0.f;

    for (int kc = 0; kc < DD; kc += BK) {
        // stage A (x): 128 rows x 64 cols, hi/lo split
#pragma unroll
        for (int it = 0; it < 8; it++) {
            int s = tid + it * 256;
            int row = s >> 4, cq = s & 15;
            float4 v = *reinterpret_cast<const float4*>(
                &x[(size_t)(m0 + row) * DD + kc + cq * 4]);
            unsigned h01, l01, h23, l23;
            split2(v.x, v.y, h01, l01);
            split2(v.z, v.w, h23, l23);
            int eo = (row * A_STR + cq * 4) * 2;
            *reinterpret_cast<uint2*>(sm + AHI_B + eo) = make_uint2(h01, h23);
            *reinterpret_cast<uint2*>(sm + ALO_B + eo) = make_uint2(l01, l23);
        }
        // stage B (w_ih): 128 rows x 64 cols
#pragma unroll
        for (int it = 0; it < 8; it++) {
            int s = tid + it * 256;
            int row = s >> 4, cq = s & 15;
            float4 v = *reinterpret_cast<const float4*>(
                &w_ih[(size_t)(g0 + row) * DD + kc + cq * 4]);
            unsigned h01, l01, h23, l23;
            split2(v.x, v.y, h01, l01);
            split2(v.z, v.w, h23, l23);
            int eo = (row * A_STR + cq * 4) * 2;
            *reinterpret_cast<uint2*>(sm + BHI_B + eo) = make_uint2(h01, h23);
            *reinterpret_cast<uint2*>(sm + BLO_B + eo) = make_uint2(l01, l23);
        }
        __syncthreads();

#pragma unroll
        for (int kk = 0; kk < BK / 16; kk++) {
            const uint32_t ko = kk * 32;
            uint32_t ahi[2][4], alo[2][4];
#pragma unroll
            for (int mt = 0; mt < 2; mt++) {
                ldsm_x4(ahi[mt][0], ahi[mt][1], ahi[mt][2], ahi[mt][3],
                        sb + AHI_B + aoff[mt] + ko);
                ldsm_x4(alo[mt][0], alo[mt][1], alo[mt][2], alo[mt][3],
                        sb + ALO_B + aoff[mt] + ko);
            }
#pragma unroll
            for (int p = 0; p < 4; p++) {
                uint32_t bhi[4], blo[4];
                ldsm_x4(bhi[0], bhi[1], bhi[2], bhi[3], sb + BHI_B + boff[p] + ko);
                ldsm_x4(blo[0], blo[1], blo[2], blo[3], sb + BLO_B + boff[p] + ko);
#pragma unroll
                for (int mt = 0; mt < 2; mt++)
#pragma unroll
                    for (int sub = 0; sub < 2; sub++) {
                        int nt = p * 2 + sub;
                        mma_bf16(d[mt][nt], ahi[mt], bhi[sub * 2], bhi[sub * 2 + 1]);
                        mma_bf16(d[mt][nt], ahi[mt], blo[sub * 2], blo[sub * 2 + 1]);
                        mma_bf16(d[mt][nt], alo[mt], bhi[sub * 2], bhi[sub * 2 + 1]);
                    }
            }
        }
        __syncthreads();
    }

    const int r = l >> 2;
    const int c2 = (l & 3) * 2;
#pragma unroll
    for (int mt = 0; mt < 2; mt++) {
#pragma unroll
        for (int nt = 0; nt < 8; nt++) {
            int lb = n_base + nt * 8 + c2;
            float b0 = bias[lb], b1 = bias[lb + 1];
            size_t m1 = (size_t)(m0 + m_base + mt * 16 + r);
            int g1 = g0 + lb;
            *reinterpret_cast<float2*>(&g_gi[m1 * G3 + g1]) =
                make_float2(d[mt][nt][0] + b0, d[mt][nt][1] + b1);
            *reinterpret_cast<float2*>(&g_gi[(m1 + 8) * G3 + g1]) =
                make_float2(d[mt][nt][2] + b0, d[mt][nt][3] + b1);
        }
    }
}

// =====================================================================
// Kernel 2: persistent GRU scan, HMMA dot (round-12 skeleton) +
//   striped arrival counters (4 per row-group, jb&3) +
//   bf16 ping-pong h exchange (epilogue emits hi/lo; staging copies).
// =====================================================================
#define KSTR 520
#define W_HI_B 0
#define W_LO_B 49920
#define H_HI_B 99840
#define H_LO_B 116480
#define RED_B  133120
#define SC_SMEM (133120 + 13056 * 4)

__global__ void __launch_bounds__(512, 1) gru_scan_kernel(
    const float* __restrict__ hxs,
    const float* __restrict__ masks,
    const float* __restrict__ w_hh,
    const float* __restrict__ b_hh,
    float* __restrict__ out)
{
    extern __shared__ char smc[];
    const uint32_t sb = smem_u32(smc);
    float* red = reinterpret_cast<float*>(smc + RED_B);

    const int tid = threadIdx.x;
    const int wid = tid >> 5;
    const int l = tid & 31;
    const int ks = wid;
    const int jb = blockIdx.x & 31;
    const int rb = blockIdx.x >> 5;
    const int n0 = rb * 16;

    const int e_dim  = tid & 15;
    const int e_rloc = (tid >> 4) & 15;
    const int e_dimg = jb * 16 + e_dim;

    // ---- stage w_hh slice once, split hi/lo ----
#pragma unroll
    for (int i = 0; i < 12; i++) {
        int s = tid + i * 512;
        int lrow = s >> 7;
        int kq = s & 127;
        int g = lrow >> 4, dloc = lrow & 15;
        float4 v = *reinterpret_cast<const float4*>(
            &w_hh[(size_t)(g * HH + jb * 16 + dloc) * HH + kq * 4]);
        unsigned h01, l01, h23, l23;
        split2(v.x, v.y, h01, l01);
        split2(v.z, v.w, h23, l23);
        int bo = lrow * (KSTR * 2) + kq * 8;
        *reinterpret_cast<uint2*>(smc + W_HI_B + bo) = make_uint2(h01, h23);
        *reinterpret_cast<uint2*>(smc + W_LO_B + bo) = make_uint2(l01, l23);
    }
    const float bh_r = (wid < 8) ? b_hh[e_dimg] : 0.f;
    const float bh_z = (wid < 8) ? b_hh[HH + e_dimg] : 0.f;
    const float bh_n = (wid < 8) ? b_hh[2 * HH + e_dimg] : 0.f;

    const uint32_t a_off = ((uint32_t)((l & 15) * KSTR + (l >> 4) * 8 + ks * 32)) * 2;
    uint32_t b_off[3];
#pragma unroll
    for (int p = 0; p < 3; p++)
        b_off[p] = ((uint32_t)((p * 16 + (l & 7) + ((l >> 4) & 1) * 8) * KSTR
                    + ((l >> 3) & 1) * 8 + ks * 32)) * 2;

    float hprev_reg = 0.f;

    for (int t = 0; t < TT; t++) {
        float e_m = 0.f, e_ir = 0.f, e_iz = 0.f, e_inn = 0.f;
        int e_mm = 0, e_n = 0;
        if (wid < 8) {
            e_n = n0 + e_rloc;
            e_mm = t * NN + e_n;
            e_m = __ldg(&masks[e_mm]);
            const float* gi = g_gi + (size_t)e_mm * G3;
            e_ir  = __ldg(&gi[e_dimg]);
            e_iz  = __ldg(&gi[HH + e_dimg]);
            e_inn = __ldg(&gi[2 * HH + e_dimg]);
            if (t == 0)
                hprev_reg = hxs[(size_t)e_n * HH + e_dimg];
        } else {
            if (t > 0) {
                if (tid == 256) {
                    const unsigned tgt = 8u * (unsigned)t;
                    const int cb = rb * 4;
                    unsigned e0, e1, e2, e3;
                    do {
                        asm volatile("ld.acquire.gpu.global.u32 %0, [%1];"
                                     : "=r"(e0) : "l"(&g_cnt[cb + 0].v) : "memory");
                        asm volatile("ld.acquire.gpu.global.u32 %0, [%1];"
                                     : "=r"(e1) : "l"(&g_cnt[cb + 1].v) : "memory");
                        asm volatile("ld.acquire.gpu.global.u32 %0, [%1];"
                                     : "=r"(e2) : "l"(&g_cnt[cb + 2].v) : "memory");
                        asm volatile("ld.acquire.gpu.global.u32 %0, [%1];"
                                     : "=r"(e3) : "l"(&g_cnt[cb + 3].v) : "memory");
                    } while (e0 < tgt || e1 < tgt || e2 < tgt || e3 < tgt);
                }
                asm volatile("bar.sync 3, 256;" ::: "memory");

                // copy bf16 h from ping-pong buffers (no split math)
                const unsigned short* bhi = g_hhi[(t + 1) & 1];
                const unsigned short* blo = g_hlo[(t + 1) & 1];
                const int lt = tid - 256;
#pragma unroll
                for (int i = 0; i < 4; i++) {
                    int s = lt + i * 256;       // 16 rows x 64 8-elem chunks
                    int row = s >> 6;
                    int kq = s & 63;
                    size_t src = (size_t)(n0 + row) * HH + kq * 8;
                    uint4 vh = __ldcg(reinterpret_cast<const uint4*>(&bhi[src]));
                    uint4 vl = __ldcg(reinterpret_cast<const uint4*>(&blo[src]));
                    int bo = row * (KSTR * 2) + kq * 16;
                    *reinterpret_cast<uint4*>(smc + H_HI_B + bo) = vh;
                    *reinterpret_cast<uint4*>(smc + H_LO_B + bo) = vl;
                }
            } else {
                // t == 0: split fp32 hxs
                const int lt = tid - 256;
#pragma unroll
                for (int i = 0; i < 8; i++) {
                    int s = lt + i * 256;
                    int row = s >> 7;
                    int kq = s & 127;
                    float4 v = __ldcg(reinterpret_cast<const float4*>(
                        &hxs[(size_t)(n0 + row) * HH + kq * 4]));
                    unsigned h01, l01, h23, l23;
                    split2(v.x, v.y, h01, l01);
                    split2(v.z, v.w, h23, l23);
                    int bo = row * (KSTR * 2) + kq * 8;
                    *reinterpret_cast<uint2*>(smc + H_HI_B + bo) = make_uint2(h01, h23);
                    *reinterpret_cast<uint2*>(smc + H_LO_B + bo) = make_uint2(l01, l23);
                }
            }
        }
        __syncthreads();

        // ======= HMMA dot =======
        float d[6][4];
#pragma unroll
        for (int nt = 0; nt < 6; nt++)
#pragma unroll
            for (int r = 0; r < 4; r++) d[nt][r] = 0.f;

#pragma unroll
        for (int kk = 0; kk < 2; kk++) {
            const uint32_t ko = kk * 32;
            uint32_t ah[4], al[4];
            ldsm_x4(ah[0], ah[1], ah[2], ah[3], sb + H_HI_B + a_off + ko);
            ldsm_x4(al[0], al[1], al[2], al[3], sb + H_LO_B + a_off + ko);
#pragma unroll
            for (int p = 0; p < 3; p++) {
                uint32_t bh[4], bl[4];
                ldsm_x4(bh[0], bh[1], bh[2], bh[3], sb + W_HI_B + b_off[p] + ko);
                ldsm_x4(bl[0], bl[1], bl[2], bl[3], sb + W_LO_B + b_off[p] + ko);
#pragma unroll
                for (int sub = 0; sub < 2; sub++) {
                    int nt = p * 2 + sub;
                    mma_bf16(d[nt], ah, bh[sub * 2], bh[sub * 2 + 1]);
                    mma_bf16(d[nt], ah, bl[sub * 2], bl[sub * 2 + 1]);
                    mma_bf16(d[nt], al, bh[sub * 2], bh[sub * 2 + 1]);
                }
            }
        }

#pragma unroll
        for (int nt = 0; nt < 6; nt++)
#pragma unroll
            for (int r = 0; r < 4; r++) {
                int n = nt * 8 + (l & 3) * 2 + (r & 1);
                int row = (l >> 2) + 8 * (r >> 1);
                red[(row * 48 + n) * 17 + (ks ^ ((row & 3) << 2))] = d[nt][r];
            }
        __syncthreads();

        // ======= epilogue (warps 0-7) =======
        if (wid < 8) {
            float p3[3];
#pragma unroll
            for (int g = 0; g < 3; g++) {
                const float* bp = &red[(e_rloc * 48 + g * 16 + e_dim) * 17];
                float s = 0.f;
#pragma unroll
                for (int k = 0; k < 16; k++) s += bp[k];
                p3[g] = s;
            }
            float ghr = p3[0] * e_m + bh_r;
            float ghz = p3[1] * e_m + bh_z;
            float ghn = p3[2] * e_m + bh_n;

            float r = fsigmoid(e_ir + ghr);
            float z = fsigmoid(e_iz + ghz);
            float nc = ftanh_fast(e_inn + r * ghn);
            float hval = e_m * hprev_reg;
            float hnew = (1.0f - z) * nc + z * hval;
            hprev_reg = hnew;

            out[(size_t)e_mm * HH + e_dimg] = hnew;
            // bf16 hi/lo for the next step's staging
            __nv_bfloat16 hh = __float2bfloat16(hnew);
            __nv_bfloat16 hl = __float2bfloat16(hnew - __bfloat162float(hh));
            const size_t hp = (size_t)e_n * HH + e_dimg;
            g_hhi[t & 1][hp] = __bfloat16_as_ushort(hh);
            g_hlo[t & 1][hp] = __bfloat16_as_ushort(hl);
            if (t == TT - 1)
                out[(size_t)TT * NN * HH + (size_t)e_n * HH + e_dimg] = hnew;

            asm volatile("bar.sync 2, 256;" ::: "memory");
            if (tid == 0 && t < TT - 1)
                asm volatile("red.release.gpu.global.add.u32 [%0], %1;"
                             :: "l"(&g_cnt[rb * 4 + (jb & 3)].v), "r"(1u) : "memory");
        }
    }
}

// =====================================================================
extern "C" void kernel_launch(void* const* d_in, const int* in_sizes, int n_in,
                              void* d_out, int out_size)
{
    const float* x      = (const float*)d_in[0];
    const float* hxs    = (const float*)d_in[1];
    const float* hxs_1  = (const float*)d_in[2];
    const float* masks  = (const float*)d_in[3];
    const float* w_ih   = (const float*)d_in[4];
    const float* w_hh   = (const float*)d_in[5];
    const float* b_ih   = (const float*)d_in[6];
    const float* b_hh   = (const float*)d_in[7];
    float* out = (float*)d_out;

    // third output: hxs_1 passthrough
    cudaMemcpyAsync(out + (size_t)(TT * NN + NN) * HH, hxs_1,
                    (size_t)NN * HH * sizeof(float), cudaMemcpyDeviceToDevice);

    // tensor-core bf16-split GEMM for gi (also resets scan counters)
    cudaFuncSetAttribute(gemm_mma_kernel,
                         cudaFuncAttributeMaxDynamicSharedMemorySize, GM_SMEM);
    gemm_mma_kernel<<<dim3(G3 / 128, (TT * NN) / 128), 256, GM_SMEM>>>(x, w_ih, b_ih);

    // persistent scan
    cudaFuncSetAttribute(gru_scan_kernel,
                         cudaFuncAttributeMaxDynamicSharedMemorySize, SC_SMEM);
    gru_scan_kernel<<<128, 512, SC_SMEM>>>(hxs, masks, w_hh, b_hh, out);
}

// round 14
// speedup vs baseline: 1.1126x; 1.1126x over previous
#include <cuda_runtime.h>
#include <cuda_bf16.h>
#include <cstdint>
#include <math.h>

// Problem dims
#define TT 128
#define NN 64
#define DD 512
#define HH 512
#define G3 1536   // 3*H

__device__ __forceinline__ float fsigmoid(float x) {
    return 1.0f / (1.0f + __expf(-x));
}
__device__ __forceinline__ float ftanh_fast(float x) {
    float ax = fabsf(x);
    float e = __expf(-2.0f * ax);
    float t = (1.0f - e) / (1.0f + e);
    return copysignf(t, x);
}

// ---------------- mma helpers (baseline PTX, no 'a' features) ----------------
__device__ __forceinline__ uint32_t smem_u32(const void* p) {
    uint32_t a;
    asm("{ .reg .u64 t; cvta.to.shared.u64 t, %1; cvt.u32.u64 %0, t; }" : "=r"(a) : "l"(p));
    return a;
}
__device__ __forceinline__ void ldsm_x4(uint32_t& r0, uint32_t& r1, uint32_t& r2,
                                        uint32_t& r3, uint32_t addr) {
    asm volatile("ldmatrix.sync.aligned.m8n8.x4.shared.b16 {%0,%1,%2,%3}, [%4];"
                 : "=r"(r0), "=r"(r1), "=r"(r2), "=r"(r3) : "r"(addr));
}
__device__ __forceinline__ void mma_bf16(float* d, const uint32_t* a,
                                         uint32_t b0, uint32_t b1) {
    asm volatile("mma.sync.aligned.m16n8k16.row.col.f32.bf16.bf16.f32 "
                 "{%0,%1,%2,%3}, {%4,%5,%6,%7}, {%8,%9}, {%0,%1,%2,%3};"
                 : "+f"(d[0]), "+f"(d[1]), "+f"(d[2]), "+f"(d[3])
                 : "r"(a[0]), "r"(a[1]), "r"(a[2]), "r"(a[3]), "r"(b0), "r"(b1));
}
__device__ __forceinline__ void split2(float a, float b, unsigned& hi, unsigned& lo) {
    __nv_bfloat16 ha = __float2bfloat16(a), hb = __float2bfloat16(b);
    hi = ((unsigned)__bfloat16_as_ushort(hb) << 16) | __bfloat16_as_ushort(ha);
    __nv_bfloat16 la = __float2bfloat16(a - __bfloat162float(ha));
    __nv_bfloat16 lb = __float2bfloat16(b - __bfloat162float(hb));
    lo = ((unsigned)__bfloat16_as_ushort(lb) << 16) | __bfloat16_as_ushort(la);
}

// ---------------- global scratch ----------------
__device__ float g_gi[(size_t)TT * NN * G3];   // gi[m][g]

struct __align__(128) PadU { unsigned v; unsigned pad[31]; };
__device__ PadU g_cnt[4];   // accumulating counter per scan row-group

// =====================================================================
// Kernel 1: tensor-core bf16-split GEMM via mma.sync.
// CTA tile 128(m) x 128(g), BK=64, 256 threads = 4x2 warps (32m x 64n).
// (round-13 version — confirmed win: halves x L2 traffic)
// =====================================================================
#define BK 64
#define A_STR 72
#define AHI_B 0
#define ALO_B 18432
#define BHI_B 36864
#define BLO_B 55296
#define BIAS_B 73728
#define GM_SMEM (73728 + 512)

__global__ void __launch_bounds__(256, 2) gemm_mma_kernel(
    const float* __restrict__ x,
    const float* __restrict__ w_ih,
    const float* __restrict__ b_ih)
{
    if (blockIdx.x == 0 && blockIdx.y == 0 && threadIdx.x < 4)
        g_cnt[threadIdx.x].v = 0;

    extern __shared__ char sm[];
    const uint32_t sb = smem_u32(sm);
    float* bias = reinterpret_cast<float*>(sm + BIAS_B);

    const int tid = threadIdx.x;
    const int wid = tid >> 5;
    const int l = tid & 31;
    const int g0 = blockIdx.x * 128;
    const int m0 = blockIdx.y * 128;
    const int m_base = (wid & 3) * 32;
    const int n_base = (wid >> 2) * 64;

    if (tid < 128) bias[tid] = b_ih[g0 + tid];

    uint32_t aoff[2], boff[4];
#pragma unroll
    for (int mt = 0; mt < 2; mt++)
        aoff[mt] = ((m_base + mt * 16 + (l & 15)) * A_STR + (l >> 4) * 8) * 2;
#pragma unroll
    for (int p = 0; p < 4; p++)
        boff[p] = ((n_base + p * 16 + (l & 7) + ((l >> 4) & 1) * 8) * A_STR
                   + ((l >> 3) & 1) * 8) * 2;

    float d[2][8][4];
#pragma unroll
    for (int mt = 0; mt < 2; mt++)
#pragma unroll
        for (int nt = 0; nt < 8; nt++)
#pragma unroll
            for (int r = 0; r < 4; r++) d[mt][nt][r] = 0.f;

    for (int kc = 0; kc < DD; kc += BK) {
#pragma unroll
        for (int it = 0; it < 8; it++) {
            int s = tid + it * 256;
            int row = s >> 4, cq = s & 15;
            float4 v = *reinterpret_cast<const float4*>(
                &x[(size_t)(m0 + row) * DD + kc + cq * 4]);
            unsigned h01, l01, h23, l23;
            split2(v.x, v.y, h01, l01);
            split2(v.z, v.w, h23, l23);
            int eo = (row * A_STR + cq * 4) * 2;
            *reinterpret_cast<uint2*>(sm + AHI_B + eo) = make_uint2(h01, h23);
            *reinterpret_cast<uint2*>(sm + ALO_B + eo) = make_uint2(l01, l23);
        }
#pragma unroll
        for (int it = 0; it < 8; it++) {
            int s = tid + it * 256;
            int row = s >> 4, cq = s & 15;
            float4 v = *reinterpret_cast<const float4*>(
                &w_ih[(size_t)(g0 + row) * DD + kc + cq * 4]);
            unsigned h01, l01, h23, l23;
            split2(v.x, v.y, h01, l01);
            split2(v.z, v.w, h23, l23);
            int eo = (row * A_STR + cq * 4) * 2;
            *reinterpret_cast<uint2*>(sm + BHI_B + eo) = make_uint2(h01, h23);
            *reinterpret_cast<uint2*>(sm + BLO_B + eo) = make_uint2(l01, l23);
        }
        __syncthreads();

#pragma unroll
        for (int kk = 0; kk < BK / 16; kk++) {
            const uint32_t ko = kk * 32;
            uint32_t ahi[2][4], alo[2][4];
#pragma unroll
            for (int mt = 0; mt < 2; mt++) {
                ldsm_x4(ahi[mt][0], ahi[mt][1], ahi[mt][2], ahi[mt][3],
                        sb + AHI_B + aoff[mt] + ko);
                ldsm_x4(alo[mt][0], alo[mt][1], alo[mt][2], alo[mt][3],
                        sb + ALO_B + aoff[mt] + ko);
            }
#pragma unroll
            for (int p = 0; p < 4; p++) {
                uint32_t bhi[4], blo[4];
                ldsm_x4(bhi[0], bhi[1], bhi[2], bhi[3], sb + BHI_B + boff[p] + ko);
                ldsm_x4(blo[0], blo[1], blo[2], blo[3], sb + BLO_B + boff[p] + ko);
#pragma unroll
                for (int mt = 0; mt < 2; mt++)
#pragma unroll
                    for (int sub = 0; sub < 2; sub++) {
                        int nt = p * 2 + sub;
                        mma_bf16(d[mt][nt], ahi[mt], bhi[sub * 2], bhi[sub * 2 + 1]);
                        mma_bf16(d[mt][nt], ahi[mt], blo[sub * 2], blo[sub * 2 + 1]);
                        mma_bf16(d[mt][nt], alo[mt], bhi[sub * 2], bhi[sub * 2 + 1]);
                    }
            }
        }
        __syncthreads();
    }

    const int r = l >> 2;
    const int c2 = (l & 3) * 2;
#pragma unroll
    for (int mt = 0; mt < 2; mt++) {
#pragma unroll
        for (int nt = 0; nt < 8; nt++) {
            int lb = n_base + nt * 8 + c2;
            float b0 = bias[lb], b1 = bias[lb + 1];
            size_t m1 = (size_t)(m0 + m_base + mt * 16 + r);
            int g1 = g0 + lb;
            *reinterpret_cast<float2*>(&g_gi[m1 * G3 + g1]) =
                make_float2(d[mt][nt][0] + b0, d[mt][nt][1] + b1);
            *reinterpret_cast<float2*>(&g_gi[(m1 + 8) * G3 + g1]) =
                make_float2(d[mt][nt][2] + b0, d[mt][nt][3] + b1);
        }
    }
}

// =====================================================================
// Kernel 2: persistent GRU scan with HMMA recurrent dot.
// (round-12 version verbatim — 505 us proven: single counter per
//  row-group, fp32 h staging with fused split, HMMA 16x48 per warp.)
// =====================================================================
#define KSTR 520
#define W_HI_B 0
#define W_LO_B 49920
#define H_HI_B 99840
#define H_LO_B 116480
#define RED_B  133120
#define SC_SMEM (133120 + 13056 * 4)

__global__ void __launch_bounds__(512, 1) gru_scan_kernel(
    const float* __restrict__ hxs,
    const float* __restrict__ masks,
    const float* __restrict__ w_hh,
    const float* __restrict__ b_hh,
    float* __restrict__ out)
{
    extern __shared__ char smc[];
    const uint32_t sb = smem_u32(smc);
    float* red = reinterpret_cast<float*>(smc + RED_B);

    const int tid = threadIdx.x;
    const int wid = tid >> 5;
    const int l = tid & 31;
    const int ks = wid;                  // k-slice 0..15
    const int jb = blockIdx.x & 31;      // dims jb*16 ..
    const int rb = blockIdx.x >> 5;      // rows rb*16 ..
    const int n0 = rb * 16;

    const int e_dim  = tid & 15;
    const int e_rloc = (tid >> 4) & 15;
    const int e_dimg = jb * 16 + e_dim;

    // ---- stage w_hh slice once, split hi/lo: 48 rows x 512 ----
#pragma unroll
    for (int i = 0; i < 12; i++) {
        int s = tid + i * 512;
        int lrow = s >> 7;
        int kq = s & 127;
        int g = lrow >> 4, dloc = lrow & 15;
        float4 v = *reinterpret_cast<const float4*>(
            &w_hh[(size_t)(g * HH + jb * 16 + dloc) * HH + kq * 4]);
        unsigned h01, l01, h23, l23;
        split2(v.x, v.y, h01, l01);
        split2(v.z, v.w, h23, l23);
        int bo = lrow * (KSTR * 2) + kq * 8;
        *reinterpret_cast<uint2*>(smc + W_HI_B + bo) = make_uint2(h01, h23);
        *reinterpret_cast<uint2*>(smc + W_LO_B + bo) = make_uint2(l01, l23);
    }
    const float bh_r = (wid < 8) ? b_hh[e_dimg] : 0.f;
    const float bh_z = (wid < 8) ? b_hh[HH + e_dimg] : 0.f;
    const float bh_n = (wid < 8) ? b_hh[2 * HH + e_dimg] : 0.f;

    const uint32_t a_off = ((uint32_t)((l & 15) * KSTR + (l >> 4) * 8 + ks * 32)) * 2;
    uint32_t b_off[3];
#pragma unroll
    for (int p = 0; p < 3; p++)
        b_off[p] = ((uint32_t)((p * 16 + (l & 7) + ((l >> 4) & 1) * 8) * KSTR
                    + ((l >> 3) & 1) * 8 + ks * 32)) * 2;

    float hprev_reg = 0.f;

    for (int t = 0; t < TT; t++) {
        float e_m = 0.f, e_ir = 0.f, e_iz = 0.f, e_inn = 0.f;
        int e_mm = 0, e_n = 0;
        if (wid < 8) {
            e_n = n0 + e_rloc;
            e_mm = t * NN + e_n;
            e_m = __ldg(&masks[e_mm]);
            const float* gi = g_gi + (size_t)e_mm * G3;
            e_ir  = __ldg(&gi[e_dimg]);
            e_iz  = __ldg(&gi[HH + e_dimg]);
            e_inn = __ldg(&gi[2 * HH + e_dimg]);
            if (t == 0)
                hprev_reg = hxs[(size_t)e_n * HH + e_dimg];
        } else {
            if (t > 0) {
                if (tid == 256) {
                    const unsigned tgt = 32u * (unsigned)t;
                    unsigned e;
                    do {
                        asm volatile("ld.acquire.gpu.global.u32 %0, [%1];"
                                     : "=r"(e) : "l"(&g_cnt[rb].v) : "memory");
                    } while (e < tgt);
                }
                asm volatile("bar.sync 3, 256;" ::: "memory");
            }
            const float* hsrc = (t == 0) ? hxs : (out + (size_t)(t - 1) * NN * HH);
            const int lt = tid - 256;
#pragma unroll
            for (int i = 0; i < 8; i++) {
                int s = lt + i * 256;        // 16 rows x 128 float4
                int row = s >> 7;
                int kq = s & 127;
                float4 v = __ldcg(reinterpret_cast<const float4*>(
                    &hsrc[(size_t)(n0 + row) * HH + kq * 4]));
                unsigned h01, l01, h23, l23;
                split2(v.x, v.y, h01, l01);
                split2(v.z, v.w, h23, l23);
                int bo = row * (KSTR * 2) + kq * 8;
                *reinterpret_cast<uint2*>(smc + H_HI_B + bo) = make_uint2(h01, h23);
                *reinterpret_cast<uint2*>(smc + H_LO_B + bo) = make_uint2(l01, l23);
            }
        }
        __syncthreads();

        // ======= HMMA dot: 16x48 partial for this warp's k-slice =======
        float d[6][4];
#pragma unroll
        for (int nt = 0; nt < 6; nt++)
#pragma unroll
            for (int r = 0; r < 4; r++) d[nt][r] = 0.f;

#pragma unroll
        for (int kk = 0; kk < 2; kk++) {
            const uint32_t ko = kk * 32;     // bytes (16 bf16)
            uint32_t ah[4], al[4];
            ldsm_x4(ah[0], ah[1], ah[2], ah[3], sb + H_HI_B + a_off + ko);
            ldsm_x4(al[0], al[1], al[2], al[3], sb + H_LO_B + a_off + ko);
#pragma unroll
            for (int p = 0; p < 3; p++) {
                uint32_t bh[4], bl[4];
                ldsm_x4(bh[0], bh[1], bh[2], bh[3], sb + W_HI_B + b_off[p] + ko);
                ldsm_x4(bl[0], bl[1], bl[2], bl[3], sb + W_LO_B + b_off[p] + ko);
#pragma unroll
                for (int sub = 0; sub < 2; sub++) {
                    int nt = p * 2 + sub;
                    mma_bf16(d[nt], ah, bh[sub * 2], bh[sub * 2 + 1]);
                    mma_bf16(d[nt], ah, bl[sub * 2], bl[sub * 2 + 1]);
                    mma_bf16(d[nt], al, bh[sub * 2], bh[sub * 2 + 1]);
                }
            }
        }

        // ---- store partials: red[(row*48 + n)*17 + (ks ^ ((row&3)<<2))] ----
#pragma unroll
        for (int nt = 0; nt < 6; nt++)
#pragma unroll
            for (int r = 0; r < 4; r++) {
                int n = nt * 8 + (l & 3) * 2 + (r & 1);
                int row = (l >> 2) + 8 * (r >> 1);
                red[(row * 48 + n) * 17 + (ks ^ ((row & 3) << 2))] = d[nt][r];
            }
        __syncthreads();

        // ======= epilogue (warps 0-7): sum 16 slices, gates, store =======
        if (wid < 8) {
            float p3[3];
#pragma unroll
            for (int g = 0; g < 3; g++) {
                const float* bp = &red[(e_rloc * 48 + g * 16 + e_dim) * 17];
                float s = 0.f;
#pragma unroll
                for (int k = 0; k < 16; k++) s += bp[k];
                p3[g] = s;
            }
            float ghr = p3[0] * e_m + bh_r;
            float ghz = p3[1] * e_m + bh_z;
            float ghn = p3[2] * e_m + bh_n;

            float r = fsigmoid(e_ir + ghr);
            float z = fsigmoid(e_iz + ghz);
            float nc = ftanh_fast(e_inn + r * ghn);
            float hval = e_m * hprev_reg;
            float hnew = (1.0f - z) * nc + z * hval;
            hprev_reg = hnew;

            out[(size_t)e_mm * HH + e_dimg] = hnew;
            if (t == TT - 1)
                out[(size_t)TT * NN * HH + (size_t)e_n * HH + e_dimg] = hnew;

            asm volatile("bar.sync 2, 256;" ::: "memory");
            if (tid == 0 && t < TT - 1)
                asm volatile("red.release.gpu.global.add.u32 [%0], %1;"
                             :: "l"(&g_cnt[rb].v), "r"(1u) : "memory");
        }
        // warps 8-15 fall through to next iteration's poll+stage
    }
}

// =====================================================================
extern "C" void kernel_launch(void* const* d_in, const int* in_sizes, int n_in,
                              void* d_out, int out_size)
{
    const float* x      = (const float*)d_in[0];
    const float* hxs    = (const float*)d_in[1];
    const float* hxs_1  = (const float*)d_in[2];
    const float* masks  = (const float*)d_in[3];
    const float* w_ih   = (const float*)d_in[4];
    const float* w_hh   = (const float*)d_in[5];
    const float* b_ih   = (const float*)d_in[6];
    const float* b_hh   = (const float*)d_in[7];
    float* out = (float*)d_out;

    // third output: hxs_1 passthrough
    cudaMemcpyAsync(out + (size_t)(TT * NN + NN) * HH, hxs_1,
                    (size_t)NN * HH * sizeof(float), cudaMemcpyDeviceToDevice);

    // tensor-core bf16-split GEMM for gi (also resets scan counters)
    cudaFuncSetAttribute(gemm_mma_kernel,
                         cudaFuncAttributeMaxDynamicSharedMemorySize, GM_SMEM);
    gemm_mma_kernel<<<dim3(G3 / 128, (TT * NN) / 128), 256, GM_SMEM>>>(x, w_ih, b_ih);

    // persistent scan (round-12 proven version)
    cudaFuncSetAttribute(gru_scan_kernel,
                         cudaFuncAttributeMaxDynamicSharedMemorySize, SC_SMEM);
    gru_scan_kernel<<<128, 512, SC_SMEM>>>(hxs, masks, w_hh, b_hh, out);
}

// round 15
// speedup vs baseline: 1.2159x; 1.0929x over previous
#include <cuda_runtime.h>
#include <cuda_bf16.h>
#include <cstdint>
#include <math.h>

// Problem dims
#define TT 128
#define NN 64
#define DD 512
#define HH 512
#define G3 1536   // 3*H

__device__ __forceinline__ float fsigmoid(float x) {
    return 1.0f / (1.0f + __expf(-x));
}
__device__ __forceinline__ float ftanh_fast(float x) {
    float ax = fabsf(x);
    float e = __expf(-2.0f * ax);
    float t = (1.0f - e) / (1.0f + e);
    return copysignf(t, x);
}

// ---------------- mma helpers (baseline PTX, no 'a' features) ----------------
__device__ __forceinline__ uint32_t smem_u32(const void* p) {
    uint32_t a;
    asm("{ .reg .u64 t; cvta.to.shared.u64 t, %1; cvt.u32.u64 %0, t; }" : "=r"(a) : "l"(p));
    return a;
}
__device__ __forceinline__ void ldsm_x4(uint32_t& r0, uint32_t& r1, uint32_t& r2,
                                        uint32_t& r3, uint32_t addr) {
    asm volatile("ldmatrix.sync.aligned.m8n8.x4.shared.b16 {%0,%1,%2,%3}, [%4];"
                 : "=r"(r0), "=r"(r1), "=r"(r2), "=r"(r3) : "r"(addr));
}
__device__ __forceinline__ void mma_bf16(float* d, const uint32_t* a,
                                         uint32_t b0, uint32_t b1) {
    asm volatile("mma.sync.aligned.m16n8k16.row.col.f32.bf16.bf16.f32 "
                 "{%0,%1,%2,%3}, {%4,%5,%6,%7}, {%8,%9}, {%0,%1,%2,%3};"
                 : "+f"(d[0]), "+f"(d[1]), "+f"(d[2]), "+f"(d[3])
                 : "r"(a[0]), "r"(a[1]), "r"(a[2]), "r"(a[3]), "r"(b0), "r"(b1));
}
__device__ __forceinline__ void split2(float a, float b, unsigned& hi, unsigned& lo) {
    __nv_bfloat16 ha = __float2bfloat16(a), hb = __float2bfloat16(b);
    hi = ((unsigned)__bfloat16_as_ushort(hb) << 16) | __bfloat16_as_ushort(ha);
    __nv_bfloat16 la = __float2bfloat16(a - __bfloat162float(ha));
    __nv_bfloat16 lb = __float2bfloat16(b - __bfloat162float(hb));
    lo = ((unsigned)__bfloat16_as_ushort(lb) << 16) | __bfloat16_as_ushort(la);
}

// ---------------- global scratch ----------------
__device__ float g_gi[(size_t)TT * NN * G3];   // gi[m][g]

struct __align__(128) PadU { unsigned v; unsigned pad[31]; };
__device__ PadU g_cnt[4];   // accumulating counter per scan row-group

// =====================================================================
// Kernel 1: tensor-core bf16-split GEMM via mma.sync.
// CTA tile 128(m) x 128(g), BK=64, 256 threads = 4x2 warps (32m x 64n).
// (round-13 version — confirmed win)
// =====================================================================
#define BK 64
#define A_STR 72
#define AHI_B 0
#define ALO_B 18432
#define BHI_B 36864
#define BLO_B 55296
#define BIAS_B 73728
#define GM_SMEM (73728 + 512)

__global__ void __launch_bounds__(256, 2) gemm_mma_kernel(
    const float* __restrict__ x,
    const float* __restrict__ w_ih,
    const float* __restrict__ b_ih)
{
    if (blockIdx.x == 0 && blockIdx.y == 0 && threadIdx.x < 4)
        g_cnt[threadIdx.x].v = 0;

    extern __shared__ char sm[];
    const uint32_t sb = smem_u32(sm);
    float* bias = reinterpret_cast<float*>(sm + BIAS_B);

    const int tid = threadIdx.x;
    const int wid = tid >> 5;
    const int l = tid & 31;
    const int g0 = blockIdx.x * 128;
    const int m0 = blockIdx.y * 128;
    const int m_base = (wid & 3) * 32;
    const int n_base = (wid >> 2) * 64;

    if (tid < 128) bias[tid] = b_ih[g0 + tid];

    uint32_t aoff[2], boff[4];
#pragma unroll
    for (int mt = 0; mt < 2; mt++)
        aoff[mt] = ((m_base + mt * 16 + (l & 15)) * A_STR + (l >> 4) * 8) * 2;
#pragma unroll
    for (int p = 0; p < 4; p++)
        boff[p] = ((n_base + p * 16 + (l & 7) + ((l >> 4) & 1) * 8) * A_STR
                   + ((l >> 3) & 1) * 8) * 2;

    float d[2][8][4];
#pragma unroll
    for (int mt = 0; mt < 2; mt++)
#pragma unroll
        for (int nt = 0; nt < 8; nt++)
#pragma unroll
            for (int r = 0; r < 4; r++) d[mt][nt][r] = 0.f;

    for (int kc = 0; kc < DD; kc += BK) {
#pragma unroll
        for (int it = 0; it < 8; it++) {
            int s = tid + it * 256;
            int row = s >> 4, cq = s & 15;
            float4 v = *reinterpret_cast<const float4*>(
                &x[(size_t)(m0 + row) * DD + kc + cq * 4]);
            unsigned h01, l01, h23, l23;
            split2(v.x, v.y, h01, l01);
            split2(v.z, v.w, h23, l23);
            int eo = (row * A_STR + cq * 4) * 2;
            *reinterpret_cast<uint2*>(sm + AHI_B + eo) = make_uint2(h01, h23);
            *reinterpret_cast<uint2*>(sm + ALO_B + eo) = make_uint2(l01, l23);
        }
#pragma unroll
        for (int it = 0; it < 8; it++) {
            int s = tid + it * 256;
            int row = s >> 4, cq = s & 15;
            float4 v = *reinterpret_cast<const float4*>(
                &w_ih[(size_t)(g0 + row) * DD + kc + cq * 4]);
            unsigned h01, l01, h23, l23;
            split2(v.x, v.y, h01, l01);
            split2(v.z, v.w, h23, l23);
            int eo = (row * A_STR + cq * 4) * 2;
            *reinterpret_cast<uint2*>(sm + BHI_B + eo) = make_uint2(h01, h23);
            *reinterpret_cast<uint2*>(sm + BLO_B + eo) = make_uint2(l01, l23);
        }
        __syncthreads();

#pragma unroll
        for (int kk = 0; kk < BK / 16; kk++) {
            const uint32_t ko = kk * 32;
            uint32_t ahi[2][4], alo[2][4];
#pragma unroll
            for (int mt = 0; mt < 2; mt++) {
                ldsm_x4(ahi[mt][0], ahi[mt][1], ahi[mt][2], ahi[mt][3],
                        sb + AHI_B + aoff[mt] + ko);
                ldsm_x4(alo[mt][0], alo[mt][1], alo[mt][2], alo[mt][3],
                        sb + ALO_B + aoff[mt] + ko);
            }
#pragma unroll
            for (int p = 0; p < 4; p++) {
                uint32_t bhi[4], blo[4];
                ldsm_x4(bhi[0], bhi[1], bhi[2], bhi[3], sb + BHI_B + boff[p] + ko);
                ldsm_x4(blo[0], blo[1], blo[2], blo[3], sb + BLO_B + boff[p] + ko);
#pragma unroll
                for (int mt = 0; mt < 2; mt++)
#pragma unroll
                    for (int sub = 0; sub < 2; sub++) {
                        int nt = p * 2 + sub;
                        mma_bf16(d[mt][nt], ahi[mt], bhi[sub * 2], bhi[sub * 2 + 1]);
                        mma_bf16(d[mt][nt], ahi[mt], blo[sub * 2], blo[sub * 2 + 1]);
                        mma_bf16(d[mt][nt], alo[mt], bhi[sub * 2], bhi[sub * 2 + 1]);
                    }
            }
        }
        __syncthreads();
    }

    const int r = l >> 2;
    const int c2 = (l & 3) * 2;
#pragma unroll
    for (int mt = 0; mt < 2; mt++) {
#pragma unroll
        for (int nt = 0; nt < 8; nt++) {
            int lb = n_base + nt * 8 + c2;
            float b0 = bias[lb], b1 = bias[lb + 1];
            size_t m1 = (size_t)(m0 + m_base + mt * 16 + r);
            int g1 = g0 + lb;
            *reinterpret_cast<float2*>(&g_gi[m1 * G3 + g1]) =
                make_float2(d[mt][nt][0] + b0, d[mt][nt][1] + b1);
            *reinterpret_cast<float2*>(&g_gi[(m1 + 8) * G3 + g1]) =
                make_float2(d[mt][nt][2] + b0, d[mt][nt][3] + b1);
        }
    }
}

// =====================================================================
// Kernel 2: persistent GRU scan, HMMA dot. Round-12 skeleton with ONE
// change: w fragments are loaded by LDSM ONCE before the t-loop and kept
// in registers (48/thread) — the per-step dot does only 4 h-LDSM,
// removing ~96KB/step of smem reads per CTA.
// =====================================================================
#define KSTR 520
#define W_HI_B 0
#define W_LO_B 49920
#define H_HI_B 99840
#define H_LO_B 116480
#define RED_B  133120
#define SC_SMEM (133120 + 13056 * 4)

__global__ void __launch_bounds__(512, 1) gru_scan_kernel(
    const float* __restrict__ hxs,
    const float* __restrict__ masks,
    const float* __restrict__ w_hh,
    const float* __restrict__ b_hh,
    float* __restrict__ out)
{
    extern __shared__ char smc[];
    const uint32_t sb = smem_u32(smc);
    float* red = reinterpret_cast<float*>(smc + RED_B);

    const int tid = threadIdx.x;
    const int wid = tid >> 5;
    const int l = tid & 31;
    const int ks = wid;                  // k-slice 0..15
    const int jb = blockIdx.x & 31;      // dims jb*16 ..
    const int rb = blockIdx.x >> 5;      // rows rb*16 ..
    const int n0 = rb * 16;

    const int e_dim  = tid & 15;
    const int e_rloc = (tid >> 4) & 15;
    const int e_dimg = jb * 16 + e_dim;

    // ---- stage w_hh slice once, split hi/lo: 48 rows x 512 ----
#pragma unroll
    for (int i = 0; i < 12; i++) {
        int s = tid + i * 512;
        int lrow = s >> 7;
        int kq = s & 127;
        int g = lrow >> 4, dloc = lrow & 15;
        float4 v = *reinterpret_cast<const float4*>(
            &w_hh[(size_t)(g * HH + jb * 16 + dloc) * HH + kq * 4]);
        unsigned h01, l01, h23, l23;
        split2(v.x, v.y, h01, l01);
        split2(v.z, v.w, h23, l23);
        int bo = lrow * (KSTR * 2) + kq * 8;
        *reinterpret_cast<uint2*>(smc + W_HI_B + bo) = make_uint2(h01, h23);
        *reinterpret_cast<uint2*>(smc + W_LO_B + bo) = make_uint2(l01, l23);
    }
    const float bh_r = (wid < 8) ? b_hh[e_dimg] : 0.f;
    const float bh_z = (wid < 8) ? b_hh[HH + e_dimg] : 0.f;
    const float bh_n = (wid < 8) ? b_hh[2 * HH + e_dimg] : 0.f;

    const uint32_t a_off = ((uint32_t)((l & 15) * KSTR + (l >> 4) * 8 + ks * 32)) * 2;
    uint32_t b_off[3];
#pragma unroll
    for (int p = 0; p < 3; p++)
        b_off[p] = ((uint32_t)((p * 16 + (l & 7) + ((l >> 4) & 1) * 8) * KSTR
                    + ((l >> 3) & 1) * 8 + ks * 32)) * 2;

    __syncthreads();

    // ---- load w fragments ONCE into registers (persistent, 48 regs) ----
    uint32_t wbh[2][3][4], wbl[2][3][4];
#pragma unroll
    for (int kk = 0; kk < 2; kk++)
#pragma unroll
        for (int p = 0; p < 3; p++) {
            ldsm_x4(wbh[kk][p][0], wbh[kk][p][1], wbh[kk][p][2], wbh[kk][p][3],
                    sb + W_HI_B + b_off[p] + kk * 32);
            ldsm_x4(wbl[kk][p][0], wbl[kk][p][1], wbl[kk][p][2], wbl[kk][p][3],
                    sb + W_LO_B + b_off[p] + kk * 32);
        }

    float hprev_reg = 0.f;

    for (int t = 0; t < TT; t++) {
        float e_m = 0.f, e_ir = 0.f, e_iz = 0.f, e_inn = 0.f;
        int e_mm = 0, e_n = 0;
        if (wid < 8) {
            e_n = n0 + e_rloc;
            e_mm = t * NN + e_n;
            e_m = __ldg(&masks[e_mm]);
            const float* gi = g_gi + (size_t)e_mm * G3;
            e_ir  = __ldg(&gi[e_dimg]);
            e_iz  = __ldg(&gi[HH + e_dimg]);
            e_inn = __ldg(&gi[2 * HH + e_dimg]);
            if (t == 0)
                hprev_reg = hxs[(size_t)e_n * HH + e_dimg];
        } else {
            if (t > 0) {
                if (tid == 256) {
                    const unsigned tgt = 32u * (unsigned)t;
                    unsigned e;
                    do {
                        asm volatile("ld.acquire.gpu.global.u32 %0, [%1];"
                                     : "=r"(e) : "l"(&g_cnt[rb].v) : "memory");
                    } while (e < tgt);
                }
                asm volatile("bar.sync 3, 256;" ::: "memory");
            }
            const float* hsrc = (t == 0) ? hxs : (out + (size_t)(t - 1) * NN * HH);
            const int lt = tid - 256;
#pragma unroll
            for (int i = 0; i < 8; i++) {
                int s = lt + i * 256;        // 16 rows x 128 float4
                int row = s >> 7;
                int kq = s & 127;
                float4 v = __ldcg(reinterpret_cast<const float4*>(
                    &hsrc[(size_t)(n0 + row) * HH + kq * 4]));
                unsigned h01, l01, h23, l23;
                split2(v.x, v.y, h01, l01);
                split2(v.z, v.w, h23, l23);
                int bo = row * (KSTR * 2) + kq * 8;
                *reinterpret_cast<uint2*>(smc + H_HI_B + bo) = make_uint2(h01, h23);
                *reinterpret_cast<uint2*>(smc + H_LO_B + bo) = make_uint2(l01, l23);
            }
        }
        __syncthreads();

        // ======= HMMA dot: 16x48 partial, w from registers =======
        float d[6][4];
#pragma unroll
        for (int nt = 0; nt < 6; nt++)
#pragma unroll
            for (int r = 0; r < 4; r++) d[nt][r] = 0.f;

#pragma unroll
        for (int kk = 0; kk < 2; kk++) {
            const uint32_t ko = kk * 32;     // bytes (16 bf16)
            uint32_t ah[4], al[4];
            ldsm_x4(ah[0], ah[1], ah[2], ah[3], sb + H_HI_B + a_off + ko);
            ldsm_x4(al[0], al[1], al[2], al[3], sb + H_LO_B + a_off + ko);
#pragma unroll
            for (int p = 0; p < 3; p++) {
#pragma unroll
                for (int sub = 0; sub < 2; sub++) {
                    int nt = p * 2 + sub;
                    mma_bf16(d[nt], ah, wbh[kk][p][sub * 2], wbh[kk][p][sub * 2 + 1]);
                    mma_bf16(d[nt], ah, wbl[kk][p][sub * 2], wbl[kk][p][sub * 2 + 1]);
                    mma_bf16(d[nt], al, wbh[kk][p][sub * 2], wbh[kk][p][sub * 2 + 1]);
                }
            }
        }

        // ---- store partials: red[(row*48 + n)*17 + (ks ^ ((row&3)<<2))] ----
#pragma unroll
        for (int nt = 0; nt < 6; nt++)
#pragma unroll
            for (int r = 0; r < 4; r++) {
                int n = nt * 8 + (l & 3) * 2 + (r & 1);
                int row = (l >> 2) + 8 * (r >> 1);
                red[(row * 48 + n) * 17 + (ks ^ ((row & 3) << 2))] = d[nt][r];
            }
        __syncthreads();

        // ======= epilogue (warps 0-7): sum 16 slices, gates, store =======
        if (wid < 8) {
            float p3[3];
#pragma unroll
            for (int g = 0; g < 3; g++) {
                const float* bp = &red[(e_rloc * 48 + g * 16 + e_dim) * 17];
                float s = 0.f;
#pragma unroll
                for (int k = 0; k < 16; k++) s += bp[k];
                p3[g] = s;
            }
            float ghr = p3[0] * e_m + bh_r;
            float ghz = p3[1] * e_m + bh_z;
            float ghn = p3[2] * e_m + bh_n;

            float r = fsigmoid(e_ir + ghr);
            float z = fsigmoid(e_iz + ghz);
            float nc = ftanh_fast(e_inn + r * ghn);
            float hval = e_m * hprev_reg;
            float hnew = (1.0f - z) * nc + z * hval;
            hprev_reg = hnew;

            out[(size_t)e_mm * HH + e_dimg] = hnew;
            if (t == TT - 1)
                out[(size_t)TT * NN * HH + (size_t)e_n * HH + e_dimg] = hnew;

            asm volatile("bar.sync 2, 256;" ::: "memory");
            if (tid == 0 && t < TT - 1)
                asm volatile("red.release.gpu.global.add.u32 [%0], %1;"
                             :: "l"(&g_cnt[rb].v), "r"(1u) : "memory");
        }
        // warps 8-15 fall through to next iteration's poll+stage
    }
}

// =====================================================================
extern "C" void kernel_launch(void* const* d_in, const int* in_sizes, int n_in,
                              void* d_out, int out_size)
{
    const float* x      = (const float*)d_in[0];
    const float* hxs    = (const float*)d_in[1];
    const float* hxs_1  = (const float*)d_in[2];
    const float* masks  = (const float*)d_in[3];
    const float* w_ih   = (const float*)d_in[4];
    const float* w_hh   = (const float*)d_in[5];
    const float* b_ih   = (const float*)d_in[6];
    const float* b_hh   = (const float*)d_in[7];
    float* out = (float*)d_out;

    // third output: hxs_1 passthrough
    cudaMemcpyAsync(out + (size_t)(TT * NN + NN) * HH, hxs_1,
                    (size_t)NN * HH * sizeof(float), cudaMemcpyDeviceToDevice);

    // tensor-core bf16-split GEMM for gi (also resets scan counters)
    cudaFuncSetAttribute(gemm_mma_kernel,
                         cudaFuncAttributeMaxDynamicSharedMemorySize, GM_SMEM);
    gemm_mma_kernel<<<dim3(G3 / 128, (TT * NN) / 128), 256, GM_SMEM>>>(x, w_ih, b_ih);

    // persistent scan (w fragments register-persistent)
    cudaFuncSetAttribute(gru_scan_kernel,
                         cudaFuncAttributeMaxDynamicSharedMemorySize, SC_SMEM);
    gru_scan_kernel<<<128, 512, SC_SMEM>>>(hxs, masks, w_hh, b_hh, out);
}

// round 16
// speedup vs baseline: 1.2534x; 1.0308x over previous
#include <cuda_runtime.h>
#include <cuda_bf16.h>
#include <cstdint>
#include <math.h>

// Problem dims
#define TT 128
#define NN 64
#define DD 512
#define HH 512
#define G3 1536   // 3*H

__device__ __forceinline__ float fsigmoid(float x) {
    return 1.0f / (1.0f + __expf(-x));
}
__device__ __forceinline__ float ftanh_fast(float x) {
    float ax = fabsf(x);
    float e = __expf(-2.0f * ax);
    float t = (1.0f - e) / (1.0f + e);
    return copysignf(t, x);
}

// ---------------- mma helpers (baseline PTX, no 'a' features) ----------------
__device__ __forceinline__ uint32_t smem_u32(const void* p) {
    uint32_t a;
    asm("{ .reg .u64 t; cvta.to.shared.u64 t, %1; cvt.u32.u64 %0, t; }" : "=r"(a) : "l"(p));
    return a;
}
__device__ __forceinline__ void ldsm_x4(uint32_t& r0, uint32_t& r1, uint32_t& r2,
                                        uint32_t& r3, uint32_t addr) {
    asm volatile("ldmatrix.sync.aligned.m8n8.x4.shared.b16 {%0,%1,%2,%3}, [%4];"
                 : "=r"(r0), "=r"(r1), "=r"(r2), "=r"(r3) : "r"(addr));
}
__device__ __forceinline__ void mma_bf16(float* d, const uint32_t* a,
                                         uint32_t b0, uint32_t b1) {
    asm volatile("mma.sync.aligned.m16n8k16.row.col.f32.bf16.bf16.f32 "
                 "{%0,%1,%2,%3}, {%4,%5,%6,%7}, {%8,%9}, {%0,%1,%2,%3};"
                 : "+f"(d[0]), "+f"(d[1]), "+f"(d[2]), "+f"(d[3])
                 : "r"(a[0]), "r"(a[1]), "r"(a[2]), "r"(a[3]), "r"(b0), "r"(b1));
}
__device__ __forceinline__ void split2(float a, float b, unsigned& hi, unsigned& lo) {
    __nv_bfloat16 ha = __float2bfloat16(a), hb = __float2bfloat16(b);
    hi = ((unsigned)__bfloat16_as_ushort(hb) << 16) | __bfloat16_as_ushort(ha);
    __nv_bfloat16 la = __float2bfloat16(a - __bfloat162float(ha));
    __nv_bfloat16 lb = __float2bfloat16(b - __bfloat162float(hb));
    lo = ((unsigned)__bfloat16_as_ushort(lb) << 16) | __bfloat16_as_ushort(la);
}

// ---------------- global scratch ----------------
__device__ float g_gi[(size_t)TT * NN * G3];   // gi[m][g]

struct __align__(128) PadU { unsigned v; unsigned pad[31]; };
__device__ PadU g_cnt[4];   // accumulating counter per scan row-group

// =====================================================================
// Kernel 1: tensor-core bf16-split GEMM via mma.sync.
// CTA tile 128(m) x 128(g), BK=64, 256 threads = 4x2 warps (32m x 64n).
// blockIdx.x==0 CTAs also copy the hxs_1 passthrough output.
// =====================================================================
#define BK 64
#define A_STR 72
#define AHI_B 0
#define ALO_B 18432
#define BHI_B 36864
#define BLO_B 55296
#define BIAS_B 73728
#define GM_SMEM (73728 + 512)

__global__ void __launch_bounds__(256, 2) gemm_mma_kernel(
    const float* __restrict__ x,
    const float* __restrict__ w_ih,
    const float* __restrict__ b_ih,
    const float* __restrict__ hxs_1,
    float* __restrict__ out)
{
    if (blockIdx.x == 0 && blockIdx.y == 0 && threadIdx.x < 4)
        g_cnt[threadIdx.x].v = 0;

    // hxs_1 passthrough (folded memcpy): 8192 float4 over 64 CTAs
    if (blockIdx.x == 0) {
        int idx = blockIdx.y * 256 + threadIdx.x;
        if (idx < (NN * HH / 4)) {
            reinterpret_cast<float4*>(out + (size_t)(TT * NN + NN) * HH)[idx] =
                reinterpret_cast<const float4*>(hxs_1)[idx];
        }
    }

    extern __shared__ char sm[];
    const uint32_t sb = smem_u32(sm);
    float* bias = reinterpret_cast<float*>(sm + BIAS_B);

    const int tid = threadIdx.x;
    const int wid = tid >> 5;
    const int l = tid & 31;
    const int g0 = blockIdx.x * 128;
    const int m0 = blockIdx.y * 128;
    const int m_base = (wid & 3) * 32;
    const int n_base = (wid >> 2) * 64;

    if (tid < 128) bias[tid] = b_ih[g0 + tid];

    uint32_t aoff[2], boff[4];
#pragma unroll
    for (int mt = 0; mt < 2; mt++)
        aoff[mt] = ((m_base + mt * 16 + (l & 15)) * A_STR + (l >> 4) * 8) * 2;
#pragma unroll
    for (int p = 0; p < 4; p++)
        boff[p] = ((n_base + p * 16 + (l & 7) + ((l >> 4) & 1) * 8) * A_STR
                   + ((l >> 3) & 1) * 8) * 2;

    float d[2][8][4];
#pragma unroll
    for (int mt = 0; mt < 2; mt++)
#pragma unroll
        for (int nt = 0; nt < 8; nt++)
#pragma unroll
            for (int r = 0; r < 4; r++) d[mt][nt][r] = 0.f;

    for (int kc = 0; kc < DD; kc += BK) {
#pragma unroll
        for (int it = 0; it < 8; it++) {
            int s = tid + it * 256;
            int row = s >> 4, cq = s & 15;
            float4 v = *reinterpret_cast<const float4*>(
                &x[(size_t)(m0 + row) * DD + kc + cq * 4]);
            unsigned h01, l01, h23, l23;
            split2(v.x, v.y, h01, l01);
            split2(v.z, v.w, h23, l23);
            int eo = (row * A_STR + cq * 4) * 2;
            *reinterpret_cast<uint2*>(sm + AHI_B + eo) = make_uint2(h01, h23);
            *reinterpret_cast<uint2*>(sm + ALO_B + eo) = make_uint2(l01, l23);
        }
#pragma unroll
        for (int it = 0; it < 8; it++) {
            int s = tid + it * 256;
            int row = s >> 4, cq = s & 15;
            float4 v = *reinterpret_cast<const float4*>(
                &w_ih[(size_t)(g0 + row) * DD + kc + cq * 4]);
            unsigned h01, l01, h23, l23;
            split2(v.x, v.y, h01, l01);
            split2(v.z, v.w, h23, l23);
            int eo = (row * A_STR + cq * 4) * 2;
            *reinterpret_cast<uint2*>(sm + BHI_B + eo) = make_uint2(h01, h23);
            *reinterpret_cast<uint2*>(sm + BLO_B + eo) = make_uint2(l01, l23);
        }
        __syncthreads();

#pragma unroll
        for (int kk = 0; kk < BK / 16; kk++) {
            const uint32_t ko = kk * 32;
            uint32_t ahi[2][4], alo[2][4];
#pragma unroll
            for (int mt = 0; mt < 2; mt++) {
                ldsm_x4(ahi[mt][0], ahi[mt][1], ahi[mt][2], ahi[mt][3],
                        sb + AHI_B + aoff[mt] + ko);
                ldsm_x4(alo[mt][0], alo[mt][1], alo[mt][2], alo[mt][3],
                        sb + ALO_B + aoff[mt] + ko);
            }
#pragma unroll
            for (int p = 0; p < 4; p++) {
                uint32_t bhi[4], blo[4];
                ldsm_x4(bhi[0], bhi[1], bhi[2], bhi[3], sb + BHI_B + boff[p] + ko);
                ldsm_x4(blo[0], blo[1], blo[2], blo[3], sb + BLO_B + boff[p] + ko);
#pragma unroll
                for (int mt = 0; mt < 2; mt++)
#pragma unroll
                    for (int sub = 0; sub < 2; sub++) {
                        int nt = p * 2 + sub;
                        mma_bf16(d[mt][nt], ahi[mt], bhi[sub * 2], bhi[sub * 2 + 1]);
                        mma_bf16(d[mt][nt], ahi[mt], blo[sub * 2], blo[sub * 2 + 1]);
                        mma_bf16(d[mt][nt], alo[mt], bhi[sub * 2], bhi[sub * 2 + 1]);
                    }
            }
        }
        __syncthreads();
    }

    const int r = l >> 2;
    const int c2 = (l & 3) * 2;
#pragma unroll
    for (int mt = 0; mt < 2; mt++) {
#pragma unroll
        for (int nt = 0; nt < 8; nt++) {
            int lb = n_base + nt * 8 + c2;
            float b0 = bias[lb], b1 = bias[lb + 1];
            size_t m1 = (size_t)(m0 + m_base + mt * 16 + r);
            int g1 = g0 + lb;
            *reinterpret_cast<float2*>(&g_gi[m1 * G3 + g1]) =
                make_float2(d[mt][nt][0] + b0, d[mt][nt][1] + b1);
            *reinterpret_cast<float2*>(&g_gi[(m1 + 8) * G3 + g1]) =
                make_float2(d[mt][nt][2] + b0, d[mt][nt][3] + b1);
        }
    }
}

// =====================================================================
// Kernel 2: persistent GRU scan, HMMA dot, w frags register-persistent.
// NEW: split-burst h staging — half1 (cols 0..255 = warps 0-7's slices)
// staged first; after one __syncthreads warps 0-7 begin their dot while
// warps 8-15 fetch+stage cols 256..511 behind bar.sync 4 (their own
// slices only), hiding half2 LDG latency under half1's dot.
// =====================================================================
#define KSTR 520
#define W_HI_B 0
#define W_LO_B 49920
#define H_HI_B 99840
#define H_LO_B 116480
#define RED_B  133120
#define SC_SMEM (133120 + 13056 * 4)

__global__ void __launch_bounds__(512, 1) gru_scan_kernel(
    const float* __restrict__ hxs,
    const float* __restrict__ masks,
    const float* __restrict__ w_hh,
    const float* __restrict__ b_hh,
    float* __restrict__ out)
{
    extern __shared__ char smc[];
    const uint32_t sb = smem_u32(smc);
    float* red = reinterpret_cast<float*>(smc + RED_B);

    const int tid = threadIdx.x;
    const int wid = tid >> 5;
    const int l = tid & 31;
    const int ks = wid;                  // k-slice 0..15
    const int jb = blockIdx.x & 31;      // dims jb*16 ..
    const int rb = blockIdx.x >> 5;      // rows rb*16 ..
    const int n0 = rb * 16;

    const int e_dim  = tid & 15;
    const int e_rloc = (tid >> 4) & 15;
    const int e_dimg = jb * 16 + e_dim;

    // ---- stage w_hh slice once, split hi/lo: 48 rows x 512 ----
#pragma unroll
    for (int i = 0; i < 12; i++) {
        int s = tid + i * 512;
        int lrow = s >> 7;
        int kq = s & 127;
        int g = lrow >> 4, dloc = lrow & 15;
        float4 v = *reinterpret_cast<const float4*>(
            &w_hh[(size_t)(g * HH + jb * 16 + dloc) * HH + kq * 4]);
        unsigned h01, l01, h23, l23;
        split2(v.x, v.y, h01, l01);
        split2(v.z, v.w, h23, l23);
        int bo = lrow * (KSTR * 2) + kq * 8;
        *reinterpret_cast<uint2*>(smc + W_HI_B + bo) = make_uint2(h01, h23);
        *reinterpret_cast<uint2*>(smc + W_LO_B + bo) = make_uint2(l01, l23);
    }
    const float bh_r = (wid < 8) ? b_hh[e_dimg] : 0.f;
    const float bh_z = (wid < 8) ? b_hh[HH + e_dimg] : 0.f;
    const float bh_n = (wid < 8) ? b_hh[2 * HH + e_dimg] : 0.f;

    const uint32_t a_off = ((uint32_t)((l & 15) * KSTR + (l >> 4) * 8 + ks * 32)) * 2;
    uint32_t b_off[3];
#pragma unroll
    for (int p = 0; p < 3; p++)
        b_off[p] = ((uint32_t)((p * 16 + (l & 7) + ((l >> 4) & 1) * 8) * KSTR
                    + ((l >> 3) & 1) * 8 + ks * 32)) * 2;

    __syncthreads();

    // ---- load w fragments ONCE into registers (persistent, 48 regs) ----
    uint32_t wbh[2][3][4], wbl[2][3][4];
#pragma unroll
    for (int kk = 0; kk < 2; kk++)
#pragma unroll
        for (int p = 0; p < 3; p++) {
            ldsm_x4(wbh[kk][p][0], wbh[kk][p][1], wbh[kk][p][2], wbh[kk][p][3],
                    sb + W_HI_B + b_off[p] + kk * 32);
            ldsm_x4(wbl[kk][p][0], wbl[kk][p][1], wbl[kk][p][2], wbl[kk][p][3],
                    sb + W_LO_B + b_off[p] + kk * 32);
        }

    float hprev_reg = 0.f;

    for (int t = 0; t < TT; t++) {
        const float* hsrc = (t == 0) ? hxs : (out + (size_t)(t - 1) * NN * HH);
        float e_m = 0.f, e_ir = 0.f, e_iz = 0.f, e_inn = 0.f;
        int e_mm = 0, e_n = 0;
        if (wid < 8) {
            e_n = n0 + e_rloc;
            e_mm = t * NN + e_n;
            e_m = __ldg(&masks[e_mm]);
            const float* gi = g_gi + (size_t)e_mm * G3;
            e_ir  = __ldg(&gi[e_dimg]);
            e_iz  = __ldg(&gi[HH + e_dimg]);
            e_inn = __ldg(&gi[2 * HH + e_dimg]);
            if (t == 0)
                hprev_reg = hxs[(size_t)e_n * HH + e_dimg];
        } else {
            if (t > 0) {
                if (tid == 256) {
                    const unsigned tgt = 32u * (unsigned)t;
                    unsigned e;
                    do {
                        asm volatile("ld.acquire.gpu.global.u32 %0, [%1];"
                                     : "=r"(e) : "l"(&g_cnt[rb].v) : "memory");
                    } while (e < tgt);
                }
                asm volatile("bar.sync 3, 256;" ::: "memory");
            }
            // ---- stage HALF 1: columns 0..255 (16 rows x 64 float4) ----
            const int lt = tid - 256;
            float4 v1[4];
#pragma unroll
            for (int i = 0; i < 4; i++) {
                int s = lt + i * 256;
                int row = s >> 6;
                int kq = s & 63;
                v1[i] = __ldcg(reinterpret_cast<const float4*>(
                    &hsrc[(size_t)(n0 + row) * HH + kq * 4]));
            }
#pragma unroll
            for (int i = 0; i < 4; i++) {
                int s = lt + i * 256;
                int row = s >> 6;
                int kq = s & 63;
                unsigned h01, l01, h23, l23;
                split2(v1[i].x, v1[i].y, h01, l01);
                split2(v1[i].z, v1[i].w, h23, l23);
                int bo = row * (KSTR * 2) + kq * 8;
                *reinterpret_cast<uint2*>(smc + H_HI_B + bo) = make_uint2(h01, h23);
                *reinterpret_cast<uint2*>(smc + H_LO_B + bo) = make_uint2(l01, l23);
            }
        }
        __syncthreads();   // half1 visible; warps 0-7 proceed to dot

        if (wid >= 8) {
            // ---- stage HALF 2: columns 256..511 (own slices) ----
            const int lt = tid - 256;
            float4 v2[4];
#pragma unroll
            for (int i = 0; i < 4; i++) {
                int s = lt + i * 256;
                int row = s >> 6;
                int kq = 64 + (s & 63);
                v2[i] = __ldcg(reinterpret_cast<const float4*>(
                    &hsrc[(size_t)(n0 + row) * HH + kq * 4]));
            }
#pragma unroll
            for (int i = 0; i < 4; i++) {
                int s = lt + i * 256;
                int row = s >> 6;
                int kq = 64 + (s & 63);
                unsigned h01, l01, h23, l23;
                split2(v2[i].x, v2[i].y, h01, l01);
                split2(v2[i].z, v2[i].w, h23, l23);
                int bo = row * (KSTR * 2) + kq * 8;
                *reinterpret_cast<uint2*>(smc + H_HI_B + bo) = make_uint2(h01, h23);
                *reinterpret_cast<uint2*>(smc + H_LO_B + bo) = make_uint2(l01, l23);
            }
            asm volatile("bar.sync 4, 256;" ::: "memory");
        }

        // ======= HMMA dot: 16x48 partial, w from registers =======
        float d[6][4];
#pragma unroll
        for (int nt = 0; nt < 6; nt++)
#pragma unroll
            for (int r = 0; r < 4; r++) d[nt][r] = 0.f;

#pragma unroll
        for (int kk = 0; kk < 2; kk++) {
            const uint32_t ko = kk * 32;     // bytes (16 bf16)
            uint32_t ah[4], al[4];
            ldsm_x4(ah[0], ah[1], ah[2], ah[3], sb + H_HI_B + a_off + ko);
            ldsm_x4(al[0], al[1], al[2], al[3], sb + H_LO_B + a_off + ko);
#pragma unroll
            for (int p = 0; p < 3; p++) {
#pragma unroll
                for (int sub = 0; sub < 2; sub++) {
                    int nt = p * 2 + sub;
                    mma_bf16(d[nt], ah, wbh[kk][p][sub * 2], wbh[kk][p][sub * 2 + 1]);
                    mma_bf16(d[nt], ah, wbl[kk][p][sub * 2], wbl[kk][p][sub * 2 + 1]);
                    mma_bf16(d[nt], al, wbh[kk][p][sub * 2], wbh[kk][p][sub * 2 + 1]);
                }
            }
        }

        // ---- store partials: red[(row*48 + n)*17 + (ks ^ ((row&3)<<2))] ----
#pragma unroll
        for (int nt = 0; nt < 6; nt++)
#pragma unroll
            for (int r = 0; r < 4; r++) {
                int n = nt * 8 + (l & 3) * 2 + (r & 1);
                int row = (l >> 2) + 8 * (r >> 1);
                red[(row * 48 + n) * 17 + (ks ^ ((row & 3) << 2))] = d[nt][r];
            }
        __syncthreads();

        // ======= epilogue (warps 0-7): sum 16 slices, gates, store =======
        if (wid < 8) {
            float p3[3];
#pragma unroll
            for (int g = 0; g < 3; g++) {
                const float* bp = &red[(e_rloc * 48 + g * 16 + e_dim) * 17];
                float s = 0.f;
#pragma unroll
                for (int k = 0; k < 16; k++) s += bp[k];
                p3[g] = s;
            }
            float ghr = p3[0] * e_m + bh_r;
            float ghz = p3[1] * e_m + bh_z;
            float ghn = p3[2] * e_m + bh_n;

            float r = fsigmoid(e_ir + ghr);
            float z = fsigmoid(e_iz + ghz);
            float nc = ftanh_fast(e_inn + r * ghn);
            float hval = e_m * hprev_reg;
            float hnew = (1.0f - z) * nc + z * hval;
            hprev_reg = hnew;

            out[(size_t)e_mm * HH + e_dimg] = hnew;
            if (t == TT - 1)
                out[(size_t)TT * NN * HH + (size_t)e_n * HH + e_dimg] = hnew;

            asm volatile("bar.sync 2, 256;" ::: "memory");
            if (tid == 0 && t < TT - 1)
                asm volatile("red.release.gpu.global.add.u32 [%0], %1;"
                             :: "l"(&g_cnt[rb].v), "r"(1u) : "memory");
        }
        // warps 8-15 fall through to next iteration's poll+stage
    }
}

// =====================================================================
extern "C" void kernel_launch(void* const* d_in, const int* in_sizes, int n_in,
                              void* d_out, int out_size)
{
    const float* x      = (const float*)d_in[0];
    const float* hxs    = (const float*)d_in[1];
    const float* hxs_1  = (const float*)d_in[2];
    const float* masks  = (const float*)d_in[3];
    const float* w_ih   = (const float*)d_in[4];
    const float* w_hh   = (const float*)d_in[5];
    const float* b_ih   = (const float*)d_in[6];
    const float* b_hh   = (const float*)d_in[7];
    float* out = (float*)d_out;

    // tensor-core bf16-split GEMM for gi
    // (also resets scan counters and copies the hxs_1 passthrough output)
    cudaFuncSetAttribute(gemm_mma_kernel,
                         cudaFuncAttributeMaxDynamicSharedMemorySize, GM_SMEM);
    gemm_mma_kernel<<<dim3(G3 / 128, (TT * NN) / 128), 256, GM_SMEM>>>(
        x, w_ih, b_ih, hxs_1, out);

    // persistent scan (split-burst h staging)
    cudaFuncSetAttribute(gru_scan_kernel,
                         cudaFuncAttributeMaxDynamicSharedMemorySize, SC_SMEM);
    gru_scan_kernel<<<128, 512, SC_SMEM>>>(hxs, masks, w_hh, b_hh, out);
}